// round 9
// baseline (speedup 1.0000x reference)
#include <cuda_runtime.h>
#include <cuda_fp16.h>
#include <cstdint>

#define Bn 8
#define Nn 128
#define Mn 128
#define En 256
#define Hn 512
#define NROWS 1024

__device__ float   g_tn[NROWS*En];
__device__ float   g_dn[NROWS*En];
__device__ float   g_tA[NROWS*Hn];
__device__ float   g_dD[NROWS*Hn];            // b1 folded in
__device__ uint32_t g_WhT[Hn*(En/2)];         // W1c^T as half2 words: [h][kp], kp=e/2

// ---------------- helpers ----------------
__device__ __forceinline__ uint32_t smem_u32(const void* p) {
    uint32_t a;
    asm("{ .reg .u64 t; cvta.to.shared.u64 t, %1; cvt.u32.u64 %0, t; }" : "=r"(a) : "l"(p));
    return a;
}
__device__ __forceinline__ float sigmoid_fast(float x) {
    float t; asm("tanh.approx.f32 %0, %1;" : "=f"(t) : "f"(x * 0.5f));
    return 0.5f * t + 0.5f;
}
__device__ __forceinline__ unsigned long long pack2(float lo, float hi) {
    unsigned long long r; asm("mov.b64 %0, {%1, %2};" : "=l"(r) : "f"(lo), "f"(hi)); return r;
}
__device__ __forceinline__ void unpack2(unsigned long long v, float& x, float& y) {
    asm("mov.b64 {%0, %1}, %2;" : "=f"(x), "=f"(y) : "l"(v));
}
__device__ __forceinline__ unsigned long long fma2(unsigned long long a,
                                                   unsigned long long b,
                                                   unsigned long long c) {
    unsigned long long d;
    asm("fma.rn.f32x2 %0, %1, %2, %3;" : "=l"(d) : "l"(a), "l"(b), "l"(c));
    return d;
}
__device__ __forceinline__ void cp16(uint32_t dst, const void* src) {
    asm volatile("cp.async.cg.shared.global [%0], [%1], 16;"
                 :: "r"(dst), "l"(src) : "memory");
}
#define CP_COMMIT() asm volatile("cp.async.commit_group;" ::: "memory")
#define CP_WAIT1()  asm volatile("cp.async.wait_group 1;" ::: "memory")
#define CP_WAIT0()  asm volatile("cp.async.wait_group 0;" ::: "memory")

__device__ __forceinline__ void ldm4(uint32_t* d, uint32_t addr) {
    asm volatile("ldmatrix.sync.aligned.m8n8.x4.shared.b16 {%0,%1,%2,%3}, [%4];"
        : "=r"(d[0]), "=r"(d[1]), "=r"(d[2]), "=r"(d[3]) : "r"(addr));
}
// fp16 MMA, fp32 accumulate: D[16x8] += A[16x16] * B[16x8]
__device__ __forceinline__ void mma16(float* c, const uint32_t* a,
                                      uint32_t b0, uint32_t b1) {
    asm volatile(
        "mma.sync.aligned.m16n8k16.row.col.f32.f16.f16.f32 "
        "{%0,%1,%2,%3}, {%4,%5,%6,%7}, {%8,%9}, {%0,%1,%2,%3};"
        : "+f"(c[0]), "+f"(c[1]), "+f"(c[2]), "+f"(c[3])
        : "r"(a[0]), "r"(a[1]), "r"(a[2]), "r"(a[3]), "r"(b0), "r"(b1));
}

// ---------------------------------------------------------------------------
// W transpose: g_WhT[h][kp] = half2(W1c[2kp][h], W1c[2kp+1][h]).
// Tiles of 64 e x 32 h, coalesced read and write. grid 64 x 256.
// ---------------------------------------------------------------------------
__global__ __launch_bounds__(256) void wh_kernel(const float* __restrict__ W1) {
    __shared__ float tile[64][33];
    const int tx = threadIdx.x & 31;
    const int p0 = (blockIdx.x & 3) * 32;      // kp block
    const int e0 = p0 * 2;                      // e block (64 wide)
    const int h0 = (blockIdx.x >> 2) * 32;
    #pragma unroll
    for (int k = 0; k < 8; k++) {
        const int e = (threadIdx.x >> 5) + k * 8;
        tile[e][tx] = W1[(size_t)(2 * En + e0 + e) * Hn + h0 + tx];
    }
    __syncthreads();
    #pragma unroll
    for (int k = 0; k < 4; k++) {
        const int idx = threadIdx.x + k * 256;
        const int hh = idx >> 5, pp = idx & 31;
        const __half2 v = __floats2half2_rn(tile[2 * pp][hh], tile[2 * pp + 1][hh]);
        g_WhT[(size_t)(h0 + hh) * (En / 2) + p0 + pp] = *(const uint32_t*)&v;
    }
}

// ---------------------------------------------------------------------------
// prep: L2-normalize rows; tA = t@W1a; dD = d@W1b + b1 (row-major, exact fp32)
// ---------------------------------------------------------------------------
__global__ __launch_bounds__(256) void prep_kernel(
    const float* __restrict__ track, const float* __restrict__ det,
    const float* __restrict__ W1, const float* __restrict__ b1)
{
    __shared__ float sX[16][En];
    __shared__ float sScale[16];
    const int tid = threadIdx.x;
    const int rb  = blockIdx.x * 16;
    const bool isT = (rb < NROWS);
    const float* src = isT ? (track + (size_t)rb * En)
                           : (det + (size_t)(rb - NROWS) * En);

    for (int idx = tid; idx < 16 * En; idx += 256)
        sX[idx >> 8][idx & 255] = src[idx];
    __syncthreads();
    {
        const int row = tid >> 4, k = tid & 15;
        float ss = 0.f;
        #pragma unroll
        for (int i = 0; i < 16; i++) { float v = sX[row][k + 16 * i]; ss += v * v; }
        #pragma unroll
        for (int o = 8; o; o >>= 1) ss += __shfl_xor_sync(0xffffffffu, ss, o);
        if (k == 0) sScale[row] = 1.0f / fmaxf(sqrtf(ss), 1e-12f);
    }
    __syncthreads();
    float* gnorm = isT ? (g_tn + (size_t)rb * En) : (g_dn + (size_t)(rb - NROWS) * En);
    for (int idx = tid; idx < 16 * En; idx += 256) {
        const int row = idx >> 8, e = idx & 255;
        float v = sX[row][e] * sScale[row];
        sX[row][e] = v;
        gnorm[idx] = v;
    }
    __syncthreads();

    const float* Wp = W1 + (isT ? 0 : (size_t)En * Hn);
    unsigned long long acc[16];
    #pragma unroll
    for (int r = 0; r < 16; r++) acc[r] = 0ull;
    #pragma unroll 4
    for (int e = 0; e < En; e++) {
        const unsigned long long w =
            *(const unsigned long long*)(Wp + (size_t)e * Hn + 2 * tid);
        #pragma unroll
        for (int r = 0; r < 16; r++)
            acc[r] = fma2(pack2(sX[r][e], sX[r][e]), w, acc[r]);
    }
    float bx = 0.f, by = 0.f;
    if (!isT) { bx = b1[2 * tid]; by = b1[2 * tid + 1]; }
    float* yout = isT ? (g_tA + (size_t)rb * Hn) : (g_dD + (size_t)(rb - NROWS) * Hn);
    #pragma unroll
    for (int r = 0; r < 16; r++) {
        float x, y; unpack2(acc[r], x, y);
        float2 v; v.x = x + bx; v.y = y + by;
        *(float2*)(yout + (size_t)r * Hn + 2 * tid) = v;
    }
}

// ---------------------------------------------------------------------------
// main: per-CTA (b, n, m-half) fp16 GEMM M=64,N=512,K=256 (m16n8k16, fp32 acc)
// ldmatrix fragments, 3-stage cp.async pipeline, fused LN/SiLU/W2 epilogue.
// smem word layout (32-bit units):
// ---------------------------------------------------------------------------
#define AP 132                       // A row stride in half2 words (128 kp + 4)
#define BRS 20                       // B row stride in half2 words (16 kp + 4)
#define BBUF (Hn*BRS)                // 10240 words per B buffer
#define F_A    0
#define F_B    8448
#define F_TA   (F_B + 3*BBUF)        // 39168
#define F_G    (F_TA + 512)
#define F_BT   (F_G + 512)
#define F_W2   (F_BT + 512)
#define F_SUM  (F_W2 + 512)
#define F_SSQ  (F_SUM + 256)
#define F_DOT  (F_SSQ + 256)
#define F_MU   (F_DOT + 256)
#define F_RS   (F_MU + 64)
#define F_TN   (F_RS + 64)
#define SMEM_WORDS (F_TN + 256)      // 42368
#define SMEM_BYTES (SMEM_WORDS * 4)  // 169472

__global__ __launch_bounds__(256, 1) void main_kernel(
    const float* __restrict__ gamma, const float* __restrict__ beta,
    const float* __restrict__ W2, const float* __restrict__ b2,
    float* __restrict__ out)
{
    extern __shared__ float sm[];
    uint32_t* sA  = (uint32_t*)sm + F_A;
    float* sTA = sm + F_TA;
    float* sG  = sm + F_G;
    float* sBt = sm + F_BT;
    float* sW2 = sm + F_W2;
    float* sSum = sm + F_SUM;
    float* sSsq = sm + F_SSQ;
    float* sDot = sm + F_DOT;
    float* sMu  = sm + F_MU;
    float* sRs  = sm + F_RS;
    float* sTn  = sm + F_TN;

    const uint32_t sbase = smem_u32(sm);
    const uint32_t sbB   = sbase + F_B * 4;

    const int tid = threadIdx.x, lane = tid & 31, warp = tid >> 5;
    const int warpm = warp >> 2, warph = warp & 3;
    const int t4 = lane & 3, g8 = lane >> 2;
    const int grp = lane >> 3, r8 = lane & 7;
    const int pr = blockIdx.x >> 1;             // b*128 + n
    const int m0 = (blockIdx.x & 1) * 64;
    const int b  = pr >> 7;

    // per-lane ldmatrix base offsets (bytes)
    const uint32_t aoff = (uint32_t)((warpm * 32 + (grp & 1) * 8 + r8) * (AP * 4)
                                     + (grp >> 1) * 16);
    const uint32_t boff = (uint32_t)((warph * 128 + (grp & 2) * 4 + r8) * (BRS * 4)
                                     + (grp & 1) * 16);

    // issue B chunks 0,1 (each: 512 n-rows x 16 kp words -> 32 KB)
    #pragma unroll
    for (int c = 0; c < 2; c++) {
        const uint32_t dstb = sbB + (uint32_t)c * (BBUF * 4);
        const uint32_t* src = g_WhT + c * 16;
        #pragma unroll
        for (int k = 0; k < 8; k++) {
            const int g = tid + k * 256;        // 0..2047 (16B units)
            const int h = g >> 2, part = g & 3;
            cp16(dstb + (uint32_t)(h * BRS + part * 4) * 4,
                 src + (size_t)h * (En / 2) + part * 4);
        }
        CP_COMMIT();
    }

    // stage constants
    for (int i = tid; i < Hn; i += 256) {
        sTA[i] = g_tA[(size_t)pr * Hn + i];
        sG[i] = gamma[i]; sBt[i] = beta[i]; sW2[i] = W2[i];
    }
    for (int i = tid; i < En; i += 256) sTn[i] = g_tn[(size_t)pr * En + i];
    __syncthreads();

    // build A = half2(|t - d|) pairs along e, [64][AP]
    const float* dnb = g_dn + ((size_t)(b * Mn + m0)) * En;
    #pragma unroll
    for (int it = 0; it < 16; it++) {
        const int idx = tid + it * 256;          // 0..4095
        const int m = idx >> 6, q = idx & 63;    // q: float4 index -> kp 2q,2q+1
        const float4 t = *(const float4*)(sTn + 4 * q);
        const float4 d = *(const float4*)(dnb + (size_t)m * En + 4 * q);
        const __half2 h0 = __floats2half2_rn(fabsf(t.x - d.x), fabsf(t.y - d.y));
        const __half2 h1 = __floats2half2_rn(fabsf(t.z - d.z), fabsf(t.w - d.w));
        uint2 v;
        v.x = *(const uint32_t*)&h0;
        v.y = *(const uint32_t*)&h1;
        *(uint2*)(sA + m * AP + 2 * q) = v;
    }

    float acc[2][16][4];
    #pragma unroll
    for (int i = 0; i < 2; i++)
        #pragma unroll
        for (int j = 0; j < 16; j++)
            #pragma unroll
            for (int q = 0; q < 4; q++) acc[i][j][q] = 0.f;

    // mainloop: 8 chunks of 32 e, 3-stage pipeline, one sync per chunk
    int buf = 0;                                 // buffer index of chunk c
    for (int c = 0; c < 8; c++) {
        if (c < 7) { CP_WAIT1(); } else { CP_WAIT0(); }
        __syncthreads();
        if (c + 2 < 8) {
            const int bn = (buf + 2 >= 3) ? buf - 1 : buf + 2;
            const uint32_t dstb = sbB + (uint32_t)bn * (BBUF * 4);
            const uint32_t* src = g_WhT + (c + 2) * 16;
            #pragma unroll
            for (int k = 0; k < 8; k++) {
                const int g = tid + k * 256;
                const int h = g >> 2, part = g & 3;
                cp16(dstb + (uint32_t)(h * BRS + part * 4) * 4,
                     src + (size_t)h * (En / 2) + part * 4);
            }
            CP_COMMIT();
        }

        const uint32_t bbase = sbB + (uint32_t)buf * (BBUF * 4) + boff;
        #pragma unroll
        for (int ks = 0; ks < 2; ks++) {
            uint32_t a0[4], a1[4];
            const uint32_t abase = sbase + aoff + (uint32_t)(c * 16 + ks * 8) * 4;
            ldm4(a0, abase);
            ldm4(a1, abase + 16 * AP * 4);
            #pragma unroll
            for (int jj = 0; jj < 8; jj++) {
                uint32_t bb[4];
                ldm4(bb, bbase + (uint32_t)jj * (16 * BRS * 4) + (uint32_t)ks * 32);
                mma16(acc[0][2 * jj],     a0, bb[0], bb[1]);
                mma16(acc[1][2 * jj],     a1, bb[0], bb[1]);
                mma16(acc[0][2 * jj + 1], a0, bb[2], bb[3]);
                mma16(acc[1][2 * jj + 1], a1, bb[2], bb[3]);
            }
        }
        buf = (buf + 1 >= 3) ? 0 : buf + 1;
    }

    // ---- epilogue pass 1: add tA + dD, LN stats ----
    const float* dDb = g_dD + ((size_t)(b * Mn + m0)) * Hn;
    #pragma unroll
    for (int i = 0; i < 2; i++) {
        #pragma unroll
        for (int h2 = 0; h2 < 2; h2++) {
            const int ml = warpm * 32 + i * 16 + 8 * h2 + g8;
            const float* drow = dDb + (size_t)ml * Hn + warph * 128 + 2 * t4;
            float sum = 0.f, ssq = 0.f;
            #pragma unroll
            for (int j = 0; j < 16; j++) {
                const int h = warph * 128 + j * 8 + 2 * t4;
                const float2 dd = *(const float2*)(drow + j * 8);
                float v0 = acc[i][j][2 * h2]     + sTA[h]     + dd.x;
                float v1 = acc[i][j][2 * h2 + 1] + sTA[h + 1] + dd.y;
                acc[i][j][2 * h2] = v0; acc[i][j][2 * h2 + 1] = v1;
                sum += v0 + v1;
                ssq += v0 * v0 + v1 * v1;
            }
            sum += __shfl_xor_sync(0xffffffffu, sum, 1);
            sum += __shfl_xor_sync(0xffffffffu, sum, 2);
            ssq += __shfl_xor_sync(0xffffffffu, ssq, 1);
            ssq += __shfl_xor_sync(0xffffffffu, ssq, 2);
            if (t4 == 0) { sSum[warph * 64 + ml] = sum; sSsq[warph * 64 + ml] = ssq; }
        }
    }
    __syncthreads();
    if (tid < 64) {
        float s = sSum[tid] + sSum[64 + tid] + sSum[128 + tid] + sSum[192 + tid];
        float q = sSsq[tid] + sSsq[64 + tid] + sSsq[128 + tid] + sSsq[192 + tid];
        const float mu  = s * (1.f / 512.f);
        const float var = q * (1.f / 512.f) - mu * mu;
        sMu[tid] = mu;
        sRs[tid] = rsqrtf(var + 1e-5f);
    }
    __syncthreads();

    // ---- epilogue pass 2: LN, SiLU, W2 dot ----
    #pragma unroll
    for (int i = 0; i < 2; i++) {
        #pragma unroll
        for (int h2 = 0; h2 < 2; h2++) {
            const int ml = warpm * 32 + i * 16 + 8 * h2 + g8;
            const float mu = sMu[ml], rs = sRs[ml];
            float dot = 0.f;
            #pragma unroll
            for (int j = 0; j < 16; j++) {
                const int h = warph * 128 + j * 8 + 2 * t4;
                const float y0 = (acc[i][j][2 * h2]     - mu) * rs * sG[h]     + sBt[h];
                const float y1 = (acc[i][j][2 * h2 + 1] - mu) * rs * sG[h + 1] + sBt[h + 1];
                dot += (y0 * sigmoid_fast(y0)) * sW2[h];
                dot += (y1 * sigmoid_fast(y1)) * sW2[h + 1];
            }
            dot += __shfl_xor_sync(0xffffffffu, dot, 1);
            dot += __shfl_xor_sync(0xffffffffu, dot, 2);
            if (t4 == 0) sDot[warph * 64 + ml] = dot;
        }
    }
    __syncthreads();
    if (tid < 64) {
        const float d = sDot[tid] + sDot[64 + tid] + sDot[128 + tid]
                      + sDot[192 + tid] + b2[0];
        out[(size_t)pr * Mn + m0 + tid] = d;
    }
}

// ---------------------------------------------------------------------------
extern "C" void kernel_launch(void* const* d_in, const int* in_sizes, int n_in,
                              void* d_out, int out_size) {
    const float* track = (const float*)d_in[0];
    const float* det   = (const float*)d_in[1];
    const float* W1    = (const float*)d_in[2];
    const float* b1    = (const float*)d_in[3];
    const float* gamma = (const float*)d_in[4];
    const float* beta  = (const float*)d_in[5];
    const float* W2    = (const float*)d_in[6];
    const float* b2    = (const float*)d_in[7];
    float* out = (float*)d_out;

    cudaFuncSetAttribute(main_kernel,
                         cudaFuncAttributeMaxDynamicSharedMemorySize, SMEM_BYTES);

    wh_kernel<<<64, 256>>>(W1);
    prep_kernel<<<128, 256>>>(track, det, W1, b1);
    main_kernel<<<2 * Bn * Nn, 256, SMEM_BYTES>>>(gamma, beta, W2, b2, out);
}

// round 13
// speedup vs baseline: 1.1104x; 1.1104x over previous
#include <cuda_runtime.h>
#include <cuda_fp16.h>
#include <cstdint>

#define Bn 8
#define Nn 128
#define Mn 128
#define En 256
#define Hn 512
#define NROWS 1024

__device__ float   g_tn[NROWS*En];
__device__ float   g_dn[NROWS*En];
__device__ float   g_tA[NROWS*Hn];
__device__ float   g_dD[NROWS*Hn];            // b1 folded in
__device__ __half2 g_Wh[(En/2)*Hn];           // W1c as half2 pairs along e: [p][h]

// ---------------- helpers ----------------
__device__ __forceinline__ uint32_t smem_u32(const void* p) {
    uint32_t a;
    asm("{ .reg .u64 t; cvta.to.shared.u64 t, %1; cvt.u32.u64 %0, t; }" : "=r"(a) : "l"(p));
    return a;
}
__device__ __forceinline__ float sigmoid_fast(float x) {
    float t; asm("tanh.approx.f32 %0, %1;" : "=f"(t) : "f"(x * 0.5f));
    return 0.5f * t + 0.5f;
}
__device__ __forceinline__ unsigned long long pack2(float lo, float hi) {
    unsigned long long r; asm("mov.b64 %0, {%1, %2};" : "=l"(r) : "f"(lo), "f"(hi)); return r;
}
__device__ __forceinline__ void unpack2(unsigned long long v, float& x, float& y) {
    asm("mov.b64 {%0, %1}, %2;" : "=f"(x), "=f"(y) : "l"(v));
}
__device__ __forceinline__ unsigned long long fma2(unsigned long long a,
                                                   unsigned long long b,
                                                   unsigned long long c) {
    unsigned long long d;
    asm("fma.rn.f32x2 %0, %1, %2, %3;" : "=l"(d) : "l"(a), "l"(b), "l"(c));
    return d;
}
__device__ __forceinline__ void cp16(uint32_t dst, const void* src) {
    asm volatile("cp.async.cg.shared.global [%0], [%1], 16;"
                 :: "r"(dst), "l"(src) : "memory");
}
#define CP_COMMIT() asm volatile("cp.async.commit_group;" ::: "memory")
#define CP_WAIT1()  asm volatile("cp.async.wait_group 1;" ::: "memory")
#define CP_WAIT0()  asm volatile("cp.async.wait_group 0;" ::: "memory")

// fp16 MMA, fp32 accumulate: D[16x8] += A[16x16] * B[16x8]
__device__ __forceinline__ void mma16(float* c, const uint32_t* a,
                                      uint32_t b0, uint32_t b1) {
    asm volatile(
        "mma.sync.aligned.m16n8k16.row.col.f32.f16.f16.f32 "
        "{%0,%1,%2,%3}, {%4,%5,%6,%7}, {%8,%9}, {%0,%1,%2,%3};"
        : "+f"(c[0]), "+f"(c[1]), "+f"(c[2]), "+f"(c[3])
        : "r"(a[0]), "r"(a[1]), "r"(a[2]), "r"(a[3]), "r"(b0), "r"(b1));
}

// ---------------------------------------------------------------------------
// Pack W1c (rows [512,768) of W1) into half2 e-pairs: g_Wh[p*Hn+h] =
// (W1c[2p][h], W1c[2p+1][h]). grid 256 x 256.
// ---------------------------------------------------------------------------
__global__ __launch_bounds__(256) void wh_kernel(const float* __restrict__ W1) {
    const int idx = blockIdx.x * 256 + threadIdx.x;   // 0..65535
    const int p = idx >> 9, h = idx & 511;
    const float w0 = W1[(size_t)(2 * En + 2 * p)     * Hn + h];
    const float w1 = W1[(size_t)(2 * En + 2 * p + 1) * Hn + h];
    g_Wh[idx] = __floats2half2_rn(w0, w1);
}

// ---------------------------------------------------------------------------
// prep: L2-normalize rows; tA = t@W1a; dD = d@W1b + b1 (row-major, exact fp32)
// ---------------------------------------------------------------------------
__global__ __launch_bounds__(256) void prep_kernel(
    const float* __restrict__ track, const float* __restrict__ det,
    const float* __restrict__ W1, const float* __restrict__ b1)
{
    __shared__ float sX[16][En];
    __shared__ float sScale[16];
    const int tid = threadIdx.x;
    const int rb  = blockIdx.x * 16;
    const bool isT = (rb < NROWS);
    const float* src = isT ? (track + (size_t)rb * En)
                           : (det + (size_t)(rb - NROWS) * En);

    for (int idx = tid; idx < 16 * En; idx += 256)
        sX[idx >> 8][idx & 255] = src[idx];
    __syncthreads();
    {
        const int row = tid >> 4, k = tid & 15;
        float ss = 0.f;
        #pragma unroll
        for (int i = 0; i < 16; i++) { float v = sX[row][k + 16 * i]; ss += v * v; }
        #pragma unroll
        for (int o = 8; o; o >>= 1) ss += __shfl_xor_sync(0xffffffffu, ss, o);
        if (k == 0) sScale[row] = 1.0f / fmaxf(sqrtf(ss), 1e-12f);
    }
    __syncthreads();
    float* gnorm = isT ? (g_tn + (size_t)rb * En) : (g_dn + (size_t)(rb - NROWS) * En);
    for (int idx = tid; idx < 16 * En; idx += 256) {
        const int row = idx >> 8, e = idx & 255;
        float v = sX[row][e] * sScale[row];
        sX[row][e] = v;
        gnorm[idx] = v;
    }
    __syncthreads();

    const float* Wp = W1 + (isT ? 0 : (size_t)En * Hn);
    unsigned long long acc[16];
    #pragma unroll
    for (int r = 0; r < 16; r++) acc[r] = 0ull;
    #pragma unroll 4
    for (int e = 0; e < En; e++) {
        const unsigned long long w =
            *(const unsigned long long*)(Wp + (size_t)e * Hn + 2 * tid);
        #pragma unroll
        for (int r = 0; r < 16; r++)
            acc[r] = fma2(pack2(sX[r][e], sX[r][e]), w, acc[r]);
    }
    float bx = 0.f, by = 0.f;
    if (!isT) { bx = b1[2 * tid]; by = b1[2 * tid + 1]; }
    float* yout = isT ? (g_tA + (size_t)rb * Hn) : (g_dD + (size_t)(rb - NROWS) * Hn);
    #pragma unroll
    for (int r = 0; r < 16; r++) {
        float x, y; unpack2(acc[r], x, y);
        float2 v; v.x = x + bx; v.y = y + by;
        *(float2*)(yout + (size_t)r * Hn + 2 * tid) = v;
    }
}

// ---------------------------------------------------------------------------
// main: per-CTA (b, n, m-half) fp16 GEMM M=64,N=512,K=256 (m16n8k16, fp32 acc)
// warp layout 1m x 8h (warp tile 64m x 64h): each B fragment feeds 4 m-frags.
// 3-buffer cp.async, one __syncthreads per chunk. Fused LN/SiLU/W2 epilogue.
// smem units: 32-bit words.
// ---------------------------------------------------------------------------
#define AP 132                  // A row stride in half2 words (128 + 4 pad)
#define BP 520                  // B pair-row stride in half2 words (512 + 8 pad)
#define BBUF (16*BP)            // 8320 words per B buffer (one 32-e chunk)
#define F_A    0
#define F_B    (64*AP)                     // 8448
#define F_TA   (F_B + 3*BBUF)              // 33408
#define F_G    (F_TA + 512)
#define F_BT   (F_G + 512)
#define F_W2   (F_BT + 512)
#define F_SUM  (F_W2 + 512)                // [8][64]
#define F_SSQ  (F_SUM + 512)
#define F_DOT  (F_SSQ + 512)
#define F_MU   (F_DOT + 512)
#define F_RS   (F_MU + 64)
#define F_TN   (F_RS + 64)
#define SMEM_WORDS (F_TN + 256)            // 38336
#define SMEM_BYTES (SMEM_WORDS * 4)        // 153344

__global__ __launch_bounds__(256, 1) void main_kernel(
    const float* __restrict__ gamma, const float* __restrict__ beta,
    const float* __restrict__ W2, const float* __restrict__ b2,
    float* __restrict__ out)
{
    extern __shared__ float sm[];
    uint32_t* sA  = (uint32_t*)sm + F_A;        // half2 words
    uint32_t* sB  = (uint32_t*)sm + F_B;        // half2 words
    float* sTA = sm + F_TA;
    float* sG  = sm + F_G;
    float* sBt = sm + F_BT;
    float* sW2 = sm + F_W2;
    float* sSum = sm + F_SUM;
    float* sSsq = sm + F_SSQ;
    float* sDot = sm + F_DOT;
    float* sMu  = sm + F_MU;
    float* sRs  = sm + F_RS;
    float* sTn  = sm + F_TN;

    const uint32_t sbB = smem_u32(sm) + F_B * 4;

    const int tid = threadIdx.x, lane = tid & 31, warp = tid >> 5;
    const int t4 = lane & 3, g8 = lane >> 2;
    const int pr = blockIdx.x >> 1;             // b*128 + n
    const int m0 = (blockIdx.x & 1) * 64;
    const int b  = pr >> 7;

    // issue B chunks 0,1 (16 pair-rows x 512 words each, contiguous rows)
    #pragma unroll
    for (int c = 0; c < 2; c++) {
        const __half2* src = g_Wh + (size_t)c * 16 * Hn;
        const uint32_t dstb = sbB + (uint32_t)c * (BBUF * 4);
        #pragma unroll
        for (int g = 0; g < 8; g++) {
            const int gr = tid + g * 256;        // 0..2047
            const int row = gr >> 7, col = (gr & 127) * 4;
            cp16(dstb + (uint32_t)(row * BP + col) * 4, src + row * Hn + col);
        }
        CP_COMMIT();
    }

    // stage constants
    for (int i = tid; i < Hn; i += 256) {
        sTA[i] = g_tA[(size_t)pr * Hn + i];
        sG[i] = gamma[i]; sBt[i] = beta[i]; sW2[i] = W2[i];
    }
    for (int i = tid; i < En; i += 256) sTn[i] = g_tn[(size_t)pr * En + i];
    __syncthreads();

    // build A = half2(|t - d|) pairs along e, [64][AP]
    const float* dnb = g_dn + ((size_t)(b * Mn + m0)) * En;
    #pragma unroll
    for (int it = 0; it < 16; it++) {
        const int idx = tid + it * 256;          // 0..4095
        const int m = idx >> 6, q = idx & 63;    // q: float4 index -> kp 2q,2q+1
        const float4 t = *(const float4*)(sTn + 4 * q);
        const float4 d = *(const float4*)(dnb + (size_t)m * En + 4 * q);
        const __half2 h0 = __floats2half2_rn(fabsf(t.x - d.x), fabsf(t.y - d.y));
        const __half2 h1 = __floats2half2_rn(fabsf(t.z - d.z), fabsf(t.w - d.w));
        uint2 v;
        v.x = *(const uint32_t*)&h0;
        v.y = *(const uint32_t*)&h1;
        *(uint2*)(sA + m * AP + 2 * q) = v;
    }

    // acc[i][j][q]: m-frag i (rows 16i..16i+15), n-frag j (h = warp*64 + 8j)
    float acc[4][8][4];
    #pragma unroll
    for (int i = 0; i < 4; i++)
        #pragma unroll
        for (int j = 0; j < 8; j++)
            #pragma unroll
            for (int q = 0; q < 4; q++) acc[i][j][q] = 0.f;

    // mainloop: 8 chunks of 32 e, 3-buffer, one sync per chunk
    for (int c = 0; c < 8; c++) {
        if (c < 7) { CP_WAIT1(); } else { CP_WAIT0(); }
        __syncthreads();
        if (c + 2 < 8) {
            const int cn = c + 2;
            const int bn = cn - (cn >= 3 ? 3 : 0) - (cn >= 6 ? 3 : 0);  // cn % 3
            const __half2* src = g_Wh + (size_t)cn * 16 * Hn;
            const uint32_t dstb = sbB + (uint32_t)bn * (BBUF * 4);
            #pragma unroll
            for (int g = 0; g < 8; g++) {
                const int gr = tid + g * 256;
                const int row = gr >> 7, col = (gr & 127) * 4;
                cp16(dstb + (uint32_t)(row * BP + col) * 4, src + row * Hn + col);
            }
            CP_COMMIT();
        }

        const int cb = c - (c >= 3 ? 3 : 0) - (c >= 6 ? 3 : 0);         // c % 3
        const uint32_t* bbuf = sB + cb * BBUF;
        #pragma unroll
        for (int ks = 0; ks < 2; ks++) {
            const int pb = c * 16 + ks * 8;       // global pair base (kp)
            uint32_t a[4][4];
            #pragma unroll
            for (int i = 0; i < 4; i++) {
                const uint32_t* ap = sA + (i * 16 + g8) * AP + pb + t4;
                a[i][0] = ap[0];
                a[i][1] = ap[8 * AP];
                a[i][2] = ap[4];
                a[i][3] = ap[8 * AP + 4];
            }
            const uint32_t* b0p = bbuf + (ks * 8 + t4) * BP + warp * 64 + g8;
            const uint32_t* b1p = b0p + 4 * BP;
            #pragma unroll
            for (int j = 0; j < 8; j++) {
                const uint32_t b0 = b0p[j * 8];
                const uint32_t b1 = b1p[j * 8];
                mma16(acc[0][j], a[0], b0, b1);
                mma16(acc[1][j], a[1], b0, b1);
                mma16(acc[2][j], a[2], b0, b1);
                mma16(acc[3][j], a[3], b0, b1);
            }
        }
    }

    // ---- epilogue pass 1: add tA + dD, LN partial stats (h-slice of 64) ----
    const float* dDb = g_dD + ((size_t)(b * Mn + m0)) * Hn;
    #pragma unroll
    for (int i = 0; i < 4; i++) {
        #pragma unroll
        for (int h2 = 0; h2 < 2; h2++) {
            const int ml = i * 16 + 8 * h2 + g8;
            const float* drow = dDb + (size_t)ml * Hn + warp * 64 + 2 * t4;
            float sum = 0.f, ssq = 0.f;
            #pragma unroll
            for (int j = 0; j < 8; j++) {
                const int h = warp * 64 + j * 8 + 2 * t4;
                const float2 dd = *(const float2*)(drow + j * 8);
                float v0 = acc[i][j][2 * h2]     + sTA[h]     + dd.x;
                float v1 = acc[i][j][2 * h2 + 1] + sTA[h + 1] + dd.y;
                acc[i][j][2 * h2] = v0; acc[i][j][2 * h2 + 1] = v1;
                sum += v0 + v1;
                ssq += v0 * v0 + v1 * v1;
            }
            sum += __shfl_xor_sync(0xffffffffu, sum, 1);
            sum += __shfl_xor_sync(0xffffffffu, sum, 2);
            ssq += __shfl_xor_sync(0xffffffffu, ssq, 1);
            ssq += __shfl_xor_sync(0xffffffffu, ssq, 2);
            if (t4 == 0) { sSum[warp * 64 + ml] = sum; sSsq[warp * 64 + ml] = ssq; }
        }
    }
    __syncthreads();
    if (tid < 64) {
        float s = 0.f, q = 0.f;
        #pragma unroll
        for (int w = 0; w < 8; w++) { s += sSum[w * 64 + tid]; q += sSsq[w * 64 + tid]; }
        const float mu  = s * (1.f / 512.f);
        const float var = q * (1.f / 512.f) - mu * mu;
        sMu[tid] = mu;
        sRs[tid] = rsqrtf(var + 1e-5f);
    }
    __syncthreads();

    // ---- epilogue pass 2: LN, SiLU, W2 dot ----
    #pragma unroll
    for (int i = 0; i < 4; i++) {
        #pragma unroll
        for (int h2 = 0; h2 < 2; h2++) {
            const int ml = i * 16 + 8 * h2 + g8;
            const float mu = sMu[ml], rs = sRs[ml];
            float dot = 0.f;
            #pragma unroll
            for (int j = 0; j < 8; j++) {
                const int h = warp * 64 + j * 8 + 2 * t4;
                const float y0 = (acc[i][j][2 * h2]     - mu) * rs * sG[h]     + sBt[h];
                const float y1 = (acc[i][j][2 * h2 + 1] - mu) * rs * sG[h + 1] + sBt[h + 1];
                dot += (y0 * sigmoid_fast(y0)) * sW2[h];
                dot += (y1 * sigmoid_fast(y1)) * sW2[h + 1];
            }
            dot += __shfl_xor_sync(0xffffffffu, dot, 1);
            dot += __shfl_xor_sync(0xffffffffu, dot, 2);
            if (t4 == 0) sDot[warp * 64 + ml] = dot;
        }
    }
    __syncthreads();
    if (tid < 64) {
        float d = b2[0];
        #pragma unroll
        for (int w = 0; w < 8; w++) d += sDot[w * 64 + tid];
        out[(size_t)pr * Mn + m0 + tid] = d;
    }
}

// ---------------------------------------------------------------------------
extern "C" void kernel_launch(void* const* d_in, const int* in_sizes, int n_in,
                              void* d_out, int out_size) {
    const float* track = (const float*)d_in[0];
    const float* det   = (const float*)d_in[1];
    const float* W1    = (const float*)d_in[2];
    const float* b1    = (const float*)d_in[3];
    const float* gamma = (const float*)d_in[4];
    const float* beta  = (const float*)d_in[5];
    const float* W2    = (const float*)d_in[6];
    const float* b2    = (const float*)d_in[7];
    float* out = (float*)d_out;

    cudaFuncSetAttribute(main_kernel,
                         cudaFuncAttributeMaxDynamicSharedMemorySize, SMEM_BYTES);

    wh_kernel<<<256, 256>>>(W1);
    prep_kernel<<<128, 256>>>(track, det, W1, b1);
    main_kernel<<<2 * Bn * Nn, 256, SMEM_BYTES>>>(gamma, beta, W2, b2, out);
}

// round 15
// speedup vs baseline: 1.1116x; 1.0011x over previous
#include <cuda_runtime.h>
#include <cuda_fp16.h>
#include <cstdint>

#define Bn 8
#define Nn 128
#define Mn 128
#define En 256
#define Hn 512
#define NROWS 1024

__device__ float   g_tn[NROWS*En];
__device__ float   g_dn[NROWS*En];
__device__ float   g_tA[NROWS*Hn];
__device__ float   g_dD[NROWS*Hn];            // b1 folded in
__device__ __half2 g_Wh[(En/2)*Hn];           // W1c as half2 pairs along e: [p][h]

// ---------------- helpers ----------------
__device__ __forceinline__ uint32_t smem_u32(const void* p) {
    uint32_t a;
    asm("{ .reg .u64 t; cvta.to.shared.u64 t, %1; cvt.u32.u64 %0, t; }" : "=r"(a) : "l"(p));
    return a;
}
__device__ __forceinline__ float sigmoid_fast(float x) {
    float t; asm("tanh.approx.f32 %0, %1;" : "=f"(t) : "f"(x * 0.5f));
    return 0.5f * t + 0.5f;
}
__device__ __forceinline__ unsigned long long pack2(float lo, float hi) {
    unsigned long long r; asm("mov.b64 %0, {%1, %2};" : "=l"(r) : "f"(lo), "f"(hi)); return r;
}
__device__ __forceinline__ void unpack2(unsigned long long v, float& x, float& y) {
    asm("mov.b64 {%0, %1}, %2;" : "=f"(x), "=f"(y) : "l"(v));
}
__device__ __forceinline__ unsigned long long fma2(unsigned long long a,
                                                   unsigned long long b,
                                                   unsigned long long c) {
    unsigned long long d;
    asm("fma.rn.f32x2 %0, %1, %2, %3;" : "=l"(d) : "l"(a), "l"(b), "l"(c));
    return d;
}
__device__ __forceinline__ void cp16(uint32_t dst, const void* src) {
    asm volatile("cp.async.cg.shared.global [%0], [%1], 16;"
                 :: "r"(dst), "l"(src) : "memory");
}
#define CP_COMMIT() asm volatile("cp.async.commit_group;" ::: "memory")
#define CP_WAIT1()  asm volatile("cp.async.wait_group 1;" ::: "memory")
#define CP_WAIT0()  asm volatile("cp.async.wait_group 0;" ::: "memory")

// fp16 MMA, fp32 accumulate: D[16x8] += A[16x16] * B[16x8]
__device__ __forceinline__ void mma16(float* c, const uint32_t* a,
                                      uint32_t b0, uint32_t b1) {
    asm volatile(
        "mma.sync.aligned.m16n8k16.row.col.f32.f16.f16.f32 "
        "{%0,%1,%2,%3}, {%4,%5,%6,%7}, {%8,%9}, {%0,%1,%2,%3};"
        : "+f"(c[0]), "+f"(c[1]), "+f"(c[2]), "+f"(c[3])
        : "r"(a[0]), "r"(a[1]), "r"(a[2]), "r"(a[3]), "r"(b0), "r"(b1));
}

// ---------------------------------------------------------------------------
// Pack W1c (rows [512,768) of W1) into half2 e-pairs: g_Wh[p*Hn+h] =
// (W1c[2p][h], W1c[2p+1][h]). grid 256 x 256.
// ---------------------------------------------------------------------------
__global__ __launch_bounds__(256) void wh_kernel(const float* __restrict__ W1) {
    const int idx = blockIdx.x * 256 + threadIdx.x;   // 0..65535
    const int p = idx >> 9, h = idx & 511;
    const float w0 = W1[(size_t)(2 * En + 2 * p)     * Hn + h];
    const float w1 = W1[(size_t)(2 * En + 2 * p + 1) * Hn + h];
    g_Wh[idx] = __floats2half2_rn(w0, w1);
}

// ---------------------------------------------------------------------------
// prep: L2-normalize rows; tA = t@W1a; dD = d@W1b + b1 (row-major, exact fp32)
// ---------------------------------------------------------------------------
__global__ __launch_bounds__(256) void prep_kernel(
    const float* __restrict__ track, const float* __restrict__ det,
    const float* __restrict__ W1, const float* __restrict__ b1)
{
    __shared__ float sX[16][En];
    __shared__ float sScale[16];
    const int tid = threadIdx.x;
    const int rb  = blockIdx.x * 16;
    const bool isT = (rb < NROWS);
    const float* src = isT ? (track + (size_t)rb * En)
                           : (det + (size_t)(rb - NROWS) * En);

    for (int idx = tid; idx < 16 * En; idx += 256)
        sX[idx >> 8][idx & 255] = src[idx];
    __syncthreads();
    {
        const int row = tid >> 4, k = tid & 15;
        float ss = 0.f;
        #pragma unroll
        for (int i = 0; i < 16; i++) { float v = sX[row][k + 16 * i]; ss += v * v; }
        #pragma unroll
        for (int o = 8; o; o >>= 1) ss += __shfl_xor_sync(0xffffffffu, ss, o);
        if (k == 0) sScale[row] = 1.0f / fmaxf(sqrtf(ss), 1e-12f);
    }
    __syncthreads();
    float* gnorm = isT ? (g_tn + (size_t)rb * En) : (g_dn + (size_t)(rb - NROWS) * En);
    for (int idx = tid; idx < 16 * En; idx += 256) {
        const int row = idx >> 8, e = idx & 255;
        float v = sX[row][e] * sScale[row];
        sX[row][e] = v;
        gnorm[idx] = v;
    }
    __syncthreads();

    const float* Wp = W1 + (isT ? 0 : (size_t)En * Hn);
    unsigned long long acc[16];
    #pragma unroll
    for (int r = 0; r < 16; r++) acc[r] = 0ull;
    #pragma unroll 4
    for (int e = 0; e < En; e++) {
        const unsigned long long w =
            *(const unsigned long long*)(Wp + (size_t)e * Hn + 2 * tid);
        #pragma unroll
        for (int r = 0; r < 16; r++)
            acc[r] = fma2(pack2(sX[r][e], sX[r][e]), w, acc[r]);
    }
    float bx = 0.f, by = 0.f;
    if (!isT) { bx = b1[2 * tid]; by = b1[2 * tid + 1]; }
    float* yout = isT ? (g_tA + (size_t)rb * Hn) : (g_dD + (size_t)(rb - NROWS) * Hn);
    #pragma unroll
    for (int r = 0; r < 16; r++) {
        float x, y; unpack2(acc[r], x, y);
        float2 v; v.x = x + bx; v.y = y + by;
        *(float2*)(yout + (size_t)r * Hn + 2 * tid) = v;
    }
}

// ---------------------------------------------------------------------------
// main: per-CTA (b, n, m-half) fp16 GEMM M=64,N=512,K=256 (m16n8k16, fp32 acc)
// warp layout 1m x 8h (warp tile 64m x 64h): each B fragment feeds 4 m-frags.
// 3-buffer cp.async, one __syncthreads per chunk. Fused LN/SiLU/W2 epilogue.
// smem units: 32-bit words.
// ---------------------------------------------------------------------------
#define AP 132                  // A row stride in half2 words (128 + 4 pad)
#define BP 520                  // B pair-row stride in half2 words (512 + 8 pad)
#define BBUF (16*BP)            // 8320 words per B buffer (one 32-e chunk)
#define F_A    0
#define F_B    (64*AP)                     // 8448
#define F_TA   (F_B + 3*BBUF)              // 33408
#define F_G    (F_TA + 512)
#define F_BT   (F_G + 512)
#define F_W2   (F_BT + 512)
#define F_SUM  (F_W2 + 512)                // [8][64]
#define F_SSQ  (F_SUM + 512)
#define F_DOT  (F_SSQ + 512)
#define F_MU   (F_DOT + 512)
#define F_RS   (F_MU + 64)
#define F_TN   (F_RS + 64)
#define SMEM_WORDS (F_TN + 256)            // 38336
#define SMEM_BYTES (SMEM_WORDS * 4)        // 153344

__global__ __launch_bounds__(256, 1) void main_kernel(
    const float* __restrict__ gamma, const float* __restrict__ beta,
    const float* __restrict__ W2, const float* __restrict__ b2,
    float* __restrict__ out)
{
    extern __shared__ float sm[];
    uint32_t* sA  = (uint32_t*)sm + F_A;        // half2 words
    uint32_t* sB  = (uint32_t*)sm + F_B;        // half2 words
    float* sTA = sm + F_TA;
    float* sG  = sm + F_G;
    float* sBt = sm + F_BT;
    float* sW2 = sm + F_W2;
    float* sSum = sm + F_SUM;
    float* sSsq = sm + F_SSQ;
    float* sDot = sm + F_DOT;
    float* sMu  = sm + F_MU;
    float* sRs  = sm + F_RS;
    float* sTn  = sm + F_TN;

    const uint32_t sbB = smem_u32(sm) + F_B * 4;

    const int tid = threadIdx.x, lane = tid & 31, warp = tid >> 5;
    const int t4 = lane & 3, g8 = lane >> 2;
    const int pr = blockIdx.x >> 1;             // b*128 + n
    const int m0 = (blockIdx.x & 1) * 64;
    const int b  = pr >> 7;

    // issue B chunks 0,1 (16 pair-rows x 512 words each, contiguous rows)
    #pragma unroll
    for (int c = 0; c < 2; c++) {
        const __half2* src = g_Wh + (size_t)c * 16 * Hn;
        const uint32_t dstb = sbB + (uint32_t)c * (BBUF * 4);
        #pragma unroll
        for (int g = 0; g < 8; g++) {
            const int gr = tid + g * 256;        // 0..2047
            const int row = gr >> 7, col = (gr & 127) * 4;
            cp16(dstb + (uint32_t)(row * BP + col) * 4, src + row * Hn + col);
        }
        CP_COMMIT();
    }

    // stage constants
    for (int i = tid; i < Hn; i += 256) {
        sTA[i] = g_tA[(size_t)pr * Hn + i];
        sG[i] = gamma[i]; sBt[i] = beta[i]; sW2[i] = W2[i];
    }
    for (int i = tid; i < En; i += 256) sTn[i] = g_tn[(size_t)pr * En + i];
    __syncthreads();

    // build A = half2(|t - d|) pairs along e, [64][AP]
    const float* dnb = g_dn + ((size_t)(b * Mn + m0)) * En;
    #pragma unroll
    for (int it = 0; it < 16; it++) {
        const int idx = tid + it * 256;          // 0..4095
        const int m = idx >> 6, q = idx & 63;    // q: float4 index -> kp 2q,2q+1
        const float4 t = *(const float4*)(sTn + 4 * q);
        const float4 d = *(const float4*)(dnb + (size_t)m * En + 4 * q);
        const __half2 h0 = __floats2half2_rn(fabsf(t.x - d.x), fabsf(t.y - d.y));
        const __half2 h1 = __floats2half2_rn(fabsf(t.z - d.z), fabsf(t.w - d.w));
        uint2 v;
        v.x = *(const uint32_t*)&h0;
        v.y = *(const uint32_t*)&h1;
        *(uint2*)(sA + m * AP + 2 * q) = v;
    }

    // acc[i][j][q]: m-frag i (rows 16i..16i+15), n-frag j (h = warp*64 + 8j)
    float acc[4][8][4];
    #pragma unroll
    for (int i = 0; i < 4; i++)
        #pragma unroll
        for (int j = 0; j < 8; j++)
            #pragma unroll
            for (int q = 0; q < 4; q++) acc[i][j][q] = 0.f;

    // mainloop: 8 chunks of 32 e, 3-buffer, one sync per chunk
    for (int c = 0; c < 8; c++) {
        if (c < 7) { CP_WAIT1(); } else { CP_WAIT0(); }
        __syncthreads();
        if (c + 2 < 8) {
            const int cn = c + 2;
            const int bn = cn - (cn >= 3 ? 3 : 0) - (cn >= 6 ? 3 : 0);  // cn % 3
            const __half2* src = g_Wh + (size_t)cn * 16 * Hn;
            const uint32_t dstb = sbB + (uint32_t)bn * (BBUF * 4);
            #pragma unroll
            for (int g = 0; g < 8; g++) {
                const int gr = tid + g * 256;
                const int row = gr >> 7, col = (gr & 127) * 4;
                cp16(dstb + (uint32_t)(row * BP + col) * 4, src + row * Hn + col);
            }
            CP_COMMIT();
        }

        const int cb = c - (c >= 3 ? 3 : 0) - (c >= 6 ? 3 : 0);         // c % 3
        const uint32_t* bbuf = sB + cb * BBUF;
        #pragma unroll
        for (int ks = 0; ks < 2; ks++) {
            const int pb = c * 16 + ks * 8;       // global pair base (kp)
            uint32_t a[4][4];
            #pragma unroll
            for (int i = 0; i < 4; i++) {
                const uint32_t* ap = sA + (i * 16 + g8) * AP + pb + t4;
                a[i][0] = ap[0];
                a[i][1] = ap[8 * AP];
                a[i][2] = ap[4];
                a[i][3] = ap[8 * AP + 4];
            }
            const uint32_t* b0p = bbuf + (ks * 8 + t4) * BP + warp * 64 + g8;
            const uint32_t* b1p = b0p + 4 * BP;
            #pragma unroll
            for (int j = 0; j < 8; j++) {
                const uint32_t b0 = b0p[j * 8];
                const uint32_t b1 = b1p[j * 8];
                mma16(acc[0][j], a[0], b0, b1);
                mma16(acc[1][j], a[1], b0, b1);
                mma16(acc[2][j], a[2], b0, b1);
                mma16(acc[3][j], a[3], b0, b1);
            }
        }
    }

    // ---- epilogue pass 1: add tA + dD, LN partial stats (h-slice of 64) ----
    const float* dDb = g_dD + ((size_t)(b * Mn + m0)) * Hn;
    #pragma unroll
    for (int i = 0; i < 4; i++) {
        #pragma unroll
        for (int h2 = 0; h2 < 2; h2++) {
            const int ml = i * 16 + 8 * h2 + g8;
            const float* drow = dDb + (size_t)ml * Hn + warp * 64 + 2 * t4;
            float sum = 0.f, ssq = 0.f;
            #pragma unroll
            for (int j = 0; j < 8; j++) {
                const int h = warp * 64 + j * 8 + 2 * t4;
                const float2 dd = *(const float2*)(drow + j * 8);
                float v0 = acc[i][j][2 * h2]     + sTA[h]     + dd.x;
                float v1 = acc[i][j][2 * h2 + 1] + sTA[h + 1] + dd.y;
                acc[i][j][2 * h2] = v0; acc[i][j][2 * h2 + 1] = v1;
                sum += v0 + v1;
                ssq += v0 * v0 + v1 * v1;
            }
            sum += __shfl_xor_sync(0xffffffffu, sum, 1);
            sum += __shfl_xor_sync(0xffffffffu, sum, 2);
            ssq += __shfl_xor_sync(0xffffffffu, ssq, 1);
            ssq += __shfl_xor_sync(0xffffffffu, ssq, 2);
            if (t4 == 0) { sSum[warp * 64 + ml] = sum; sSsq[warp * 64 + ml] = ssq; }
        }
    }
    __syncthreads();
    if (tid < 64) {
        float s = 0.f, q = 0.f;
        #pragma unroll
        for (int w = 0; w < 8; w++) { s += sSum[w * 64 + tid]; q += sSsq[w * 64 + tid]; }
        const float mu  = s * (1.f / 512.f);
        const float var = q * (1.f / 512.f) - mu * mu;
        sMu[tid] = mu;
        sRs[tid] = rsqrtf(var + 1e-5f);
    }
    __syncthreads();

    // ---- epilogue pass 2: LN, SiLU, W2 dot ----
    #pragma unroll
    for (int i = 0; i < 4; i++) {
        #pragma unroll
        for (int h2 = 0; h2 < 2; h2++) {
            const int ml = i * 16 + 8 * h2 + g8;
            const float mu = sMu[ml], rs = sRs[ml];
            float dot = 0.f;
            #pragma unroll
            for (int j = 0; j < 8; j++) {
                const int h = warp * 64 + j * 8 + 2 * t4;
                const float y0 = (acc[i][j][2 * h2]     - mu) * rs * sG[h]     + sBt[h];
                const float y1 = (acc[i][j][2 * h2 + 1] - mu) * rs * sG[h + 1] + sBt[h + 1];
                dot += (y0 * sigmoid_fast(y0)) * sW2[h];
                dot += (y1 * sigmoid_fast(y1)) * sW2[h + 1];
            }
            dot += __shfl_xor_sync(0xffffffffu, dot, 1);
            dot += __shfl_xor_sync(0xffffffffu, dot, 2);
            if (t4 == 0) sDot[warp * 64 + ml] = dot;
        }
    }
    __syncthreads();
    if (tid < 64) {
        float d = b2[0];
        #pragma unroll
        for (int w = 0; w < 8; w++) d += sDot[w * 64 + tid];
        out[(size_t)pr * Mn + m0 + tid] = d;
    }
}

// ---------------------------------------------------------------------------
extern "C" void kernel_launch(void* const* d_in, const int* in_sizes, int n_in,
                              void* d_out, int out_size) {
    const float* track = (const float*)d_in[0];
    const float* det   = (const float*)d_in[1];
    const float* W1    = (const float*)d_in[2];
    const float* b1    = (const float*)d_in[3];
    const float* gamma = (const float*)d_in[4];
    const float* beta  = (const float*)d_in[5];
    const float* W2    = (const float*)d_in[6];
    const float* b2    = (const float*)d_in[7];
    float* out = (float*)d_out;

    cudaFuncSetAttribute(main_kernel,
                         cudaFuncAttributeMaxDynamicSharedMemorySize, SMEM_BYTES);

    wh_kernel<<<256, 256>>>(W1);
    prep_kernel<<<128, 256>>>(track, det, W1, b1);
    main_kernel<<<2 * Bn * Nn, 256, SMEM_BYTES>>>(gamma, beta, W2, b2, out);
}

// round 16
// speedup vs baseline: 1.3170x; 1.1848x over previous
#include <cuda_runtime.h>
#include <cuda_fp16.h>
#include <cstdint>

#define Bn 8
#define Nn 128
#define Mn 128
#define En 256
#define Hn 512
#define NROWS 1024

__device__ float   g_tn[NROWS*En];
__device__ float   g_dn[NROWS*En];
__device__ float   g_tA[NROWS*Hn];
__device__ float   g_dD[NROWS*Hn];            // b1 folded in
__device__ __half2 g_Wh[(En/2)*Hn];           // W1c as half2 pairs along e: [p][h]

// ---------------- helpers ----------------
__device__ __forceinline__ uint32_t smem_u32(const void* p) {
    uint32_t a;
    asm("{ .reg .u64 t; cvta.to.shared.u64 t, %1; cvt.u32.u64 %0, t; }" : "=r"(a) : "l"(p));
    return a;
}
__device__ __forceinline__ float sigmoid_fast(float x) {
    float t; asm("tanh.approx.f32 %0, %1;" : "=f"(t) : "f"(x * 0.5f));
    return 0.5f * t + 0.5f;
}
__device__ __forceinline__ unsigned long long pack2(float lo, float hi) {
    unsigned long long r; asm("mov.b64 %0, {%1, %2};" : "=l"(r) : "f"(lo), "f"(hi)); return r;
}
__device__ __forceinline__ void unpack2(unsigned long long v, float& x, float& y) {
    asm("mov.b64 {%0, %1}, %2;" : "=f"(x), "=f"(y) : "l"(v));
}
__device__ __forceinline__ unsigned long long fma2(unsigned long long a,
                                                   unsigned long long b,
                                                   unsigned long long c) {
    unsigned long long d;
    asm("fma.rn.f32x2 %0, %1, %2, %3;" : "=l"(d) : "l"(a), "l"(b), "l"(c));
    return d;
}
__device__ __forceinline__ void cp16(uint32_t dst, const void* src) {
    asm volatile("cp.async.cg.shared.global [%0], [%1], 16;"
                 :: "r"(dst), "l"(src) : "memory");
}
#define CP_COMMIT() asm volatile("cp.async.commit_group;" ::: "memory")
#define CP_WAIT1()  asm volatile("cp.async.wait_group 1;" ::: "memory")
#define CP_WAIT0()  asm volatile("cp.async.wait_group 0;" ::: "memory")

// fp16 MMA, fp16 accumulate: D[16x8] += A[16x16]*B[16x8], D/C packed half2
__device__ __forceinline__ void mma16h(uint32_t* c, const uint32_t* a,
                                       uint32_t b0, uint32_t b1) {
    asm volatile(
        "mma.sync.aligned.m16n8k16.row.col.f16.f16.f16.f16 "
        "{%0,%1}, {%2,%3,%4,%5}, {%6,%7}, {%0,%1};"
        : "+r"(c[0]), "+r"(c[1])
        : "r"(a[0]), "r"(a[1]), "r"(a[2]), "r"(a[3]), "r"(b0), "r"(b1));
}

// ---------------------------------------------------------------------------
// Pack W1c (rows [512,768) of W1) into half2 e-pairs: g_Wh[p*Hn+h] =
// (W1c[2p][h], W1c[2p+1][h]). grid 256 x 256.
// ---------------------------------------------------------------------------
__global__ __launch_bounds__(256) void wh_kernel(const float* __restrict__ W1) {
    const int idx = blockIdx.x * 256 + threadIdx.x;   // 0..65535
    const int p = idx >> 9, h = idx & 511;
    const float w0 = W1[(size_t)(2 * En + 2 * p)     * Hn + h];
    const float w1 = W1[(size_t)(2 * En + 2 * p + 1) * Hn + h];
    g_Wh[idx] = __floats2half2_rn(w0, w1);
}

// ---------------------------------------------------------------------------
// prep: L2-normalize rows; tA = t@W1a; dD = d@W1b + b1 (row-major, exact fp32)
// ---------------------------------------------------------------------------
__global__ __launch_bounds__(256) void prep_kernel(
    const float* __restrict__ track, const float* __restrict__ det,
    const float* __restrict__ W1, const float* __restrict__ b1)
{
    __shared__ float sX[16][En];
    __shared__ float sScale[16];
    const int tid = threadIdx.x;
    const int rb  = blockIdx.x * 16;
    const bool isT = (rb < NROWS);
    const float* src = isT ? (track + (size_t)rb * En)
                           : (det + (size_t)(rb - NROWS) * En);

    for (int idx = tid; idx < 16 * En; idx += 256)
        sX[idx >> 8][idx & 255] = src[idx];
    __syncthreads();
    {
        const int row = tid >> 4, k = tid & 15;
        float ss = 0.f;
        #pragma unroll
        for (int i = 0; i < 16; i++) { float v = sX[row][k + 16 * i]; ss += v * v; }
        #pragma unroll
        for (int o = 8; o; o >>= 1) ss += __shfl_xor_sync(0xffffffffu, ss, o);
        if (k == 0) sScale[row] = 1.0f / fmaxf(sqrtf(ss), 1e-12f);
    }
    __syncthreads();
    float* gnorm = isT ? (g_tn + (size_t)rb * En) : (g_dn + (size_t)(rb - NROWS) * En);
    for (int idx = tid; idx < 16 * En; idx += 256) {
        const int row = idx >> 8, e = idx & 255;
        float v = sX[row][e] * sScale[row];
        sX[row][e] = v;
        gnorm[idx] = v;
    }
    __syncthreads();

    const float* Wp = W1 + (isT ? 0 : (size_t)En * Hn);
    unsigned long long acc[16];
    #pragma unroll
    for (int r = 0; r < 16; r++) acc[r] = 0ull;
    #pragma unroll 4
    for (int e = 0; e < En; e++) {
        const unsigned long long w =
            *(const unsigned long long*)(Wp + (size_t)e * Hn + 2 * tid);
        #pragma unroll
        for (int r = 0; r < 16; r++)
            acc[r] = fma2(pack2(sX[r][e], sX[r][e]), w, acc[r]);
    }
    float bx = 0.f, by = 0.f;
    if (!isT) { bx = b1[2 * tid]; by = b1[2 * tid + 1]; }
    float* yout = isT ? (g_tA + (size_t)rb * Hn) : (g_dD + (size_t)(rb - NROWS) * Hn);
    #pragma unroll
    for (int r = 0; r < 16; r++) {
        float x, y; unpack2(acc[r], x, y);
        float2 v; v.x = x + bx; v.y = y + by;
        *(float2*)(yout + (size_t)r * Hn + 2 * tid) = v;
    }
}

// ---------------------------------------------------------------------------
// main: per-CTA (b, n, m-half) fp16 GEMM M=64,N=512,K=256 (m16n8k16,
// fp16 accum -> 64 acc regs -> 2 CTAs/SM). warps 2(m) x 4(h).
// Epilogue: pass1 fp32 v=acc+tA+dD, stats, stash v half2 in dead B smem;
// pass2 LN/SiLU/W2-dot. smem units: 32-bit words.
// ---------------------------------------------------------------------------
#define AP 132                  // A row stride in half2 words (128 + 4 pad)
#define BP 520                  // B pair-row stride in half2 words (512 + 8 pad)
#define F_A    0
#define F_B    (64*AP)                     // 8448
#define F_TA   (F_B + 2*16*BP)             // 25088
#define F_G    (F_TA + 512)
#define F_BT   (F_G + 512)
#define F_W2   (F_BT + 512)
#define F_SUM  (F_W2 + 512)                // [4][64]
#define F_SSQ  (F_SUM + 256)
#define F_DOT  (F_SSQ + 256)
#define F_MU   (F_DOT + 256)
#define F_RS   (F_MU + 64)
#define F_TN   (F_RS + 64)
#define SMEM_WORDS (F_TN + 256)            // 28288
#define SMEM_BYTES (SMEM_WORDS * 4)        // 113152

__global__ __launch_bounds__(256, 2) void main_kernel(
    const float* __restrict__ gamma, const float* __restrict__ beta,
    const float* __restrict__ W2, const float* __restrict__ b2,
    float* __restrict__ out)
{
    extern __shared__ float sm[];
    uint32_t* sA  = (uint32_t*)sm + F_A;        // half2 words
    uint32_t* sB  = (uint32_t*)sm + F_B;        // half2 words
    float* sTA = sm + F_TA;
    float* sG  = sm + F_G;
    float* sBt = sm + F_BT;
    float* sW2 = sm + F_W2;
    float* sSum = sm + F_SUM;
    float* sSsq = sm + F_SSQ;
    float* sDot = sm + F_DOT;
    float* sMu  = sm + F_MU;
    float* sRs  = sm + F_RS;
    float* sTn  = sm + F_TN;

    const uint32_t sbB = smem_u32(sm) + F_B * 4;

    const int tid = threadIdx.x, lane = tid & 31, warp = tid >> 5;
    const int warpm = warp >> 2, warph = warp & 3;
    const int t4 = lane & 3, g8 = lane >> 2;
    const int pr = blockIdx.x >> 1;             // b*128 + n
    const int m0 = (blockIdx.x & 1) * 64;
    const int b  = pr >> 7;

    // prefetch B chunks 0,1 (16 pair-rows x 512 words each, contiguous rows)
    #pragma unroll
    for (int c = 0; c < 2; c++) {
        const __half2* src = g_Wh + (size_t)c * 16 * Hn;
        const uint32_t dstb = sbB + (uint32_t)(c & 1) * (16 * BP * 4);
        #pragma unroll
        for (int g = 0; g < 8; g++) {
            const int gr = tid + g * 256;        // 0..2047
            const int row = gr >> 7, col = (gr & 127) * 4;
            cp16(dstb + (uint32_t)(row * BP + col) * 4, src + row * Hn + col);
        }
        CP_COMMIT();
    }

    // stage constants
    for (int i = tid; i < Hn; i += 256) {
        sTA[i] = g_tA[(size_t)pr * Hn + i];
        sG[i] = gamma[i]; sBt[i] = beta[i]; sW2[i] = W2[i];
    }
    for (int i = tid; i < En; i += 256) sTn[i] = g_tn[(size_t)pr * En + i];
    __syncthreads();

    // build A = half2(|t - d|) pairs along e, [64][AP]
    const float* dnb = g_dn + ((size_t)(b * Mn + m0)) * En;
    #pragma unroll
    for (int it = 0; it < 16; it++) {
        const int idx = tid + it * 256;          // 0..4095
        const int m = idx >> 6, q = idx & 63;    // q: float4 index -> kp 2q,2q+1
        const float4 t = *(const float4*)(sTn + 4 * q);
        const float4 d = *(const float4*)(dnb + (size_t)m * En + 4 * q);
        const __half2 h0 = __floats2half2_rn(fabsf(t.x - d.x), fabsf(t.y - d.y));
        const __half2 h1 = __floats2half2_rn(fabsf(t.z - d.z), fabsf(t.w - d.w));
        uint2 v;
        v.x = *(const uint32_t*)&h0;
        v.y = *(const uint32_t*)&h1;
        *(uint2*)(sA + m * AP + 2 * q) = v;
    }

    // acc16[i][j][h2]: half2 {(row,2t4),(row,2t4+1)}, row = 16i + 8*h2 + g8
    uint32_t acc16[2][16][2];
    #pragma unroll
    for (int i = 0; i < 2; i++)
        #pragma unroll
        for (int j = 0; j < 16; j++) { acc16[i][j][0] = 0u; acc16[i][j][1] = 0u; }

    // mainloop: 8 chunks of 32 e, double-buffered cp.async
    for (int c = 0; c < 8; c++) {
        if (c < 7) { CP_WAIT1(); } else { CP_WAIT0(); }
        __syncthreads();
        const uint32_t* bbuf = sB + (c & 1) * (16 * BP);
        #pragma unroll
        for (int ks = 0; ks < 2; ks++) {
            const int pb = c * 16 + ks * 8;       // global pair base (kp)
            uint32_t a[2][4];
            #pragma unroll
            for (int i = 0; i < 2; i++) {
                const uint32_t* ap = sA + (warpm * 32 + i * 16 + g8) * AP + pb + t4;
                a[i][0] = ap[0];
                a[i][1] = ap[8 * AP];
                a[i][2] = ap[4];
                a[i][3] = ap[8 * AP + 4];
            }
            const uint32_t* b0p = bbuf + (ks * 8 + t4) * BP + warph * 128 + g8;
            const uint32_t* b1p = b0p + 4 * BP;
            #pragma unroll
            for (int j = 0; j < 16; j++) {
                const uint32_t b0 = b0p[j * 8];
                const uint32_t b1 = b1p[j * 8];
                mma16h(acc16[0][j], a[0], b0, b1);
                mma16h(acc16[1][j], a[1], b0, b1);
            }
        }
        __syncthreads();
        if (c + 2 < 8) {
            const int cn = c + 2;
            const __half2* src = g_Wh + (size_t)cn * 16 * Hn;
            const uint32_t dstb = sbB + (uint32_t)(cn & 1) * (16 * BP * 4);
            #pragma unroll
            for (int g = 0; g < 8; g++) {
                const int gr = tid + g * 256;
                const int row = gr >> 7, col = (gr & 127) * 4;
                cp16(dstb + (uint32_t)(row * BP + col) * 4, src + row * Hn + col);
            }
            CP_COMMIT();
        }
    }
    __syncthreads();   // all warps done reading B -> region reusable for v

    // v stash region (thread-private, conflict-free): word = vidx*256 + tid
    uint32_t* sV = (uint32_t*)sm + F_B;

    // ---- epilogue pass 1: v = acc + tA + dD (fp32), stats, stash v ----
    const float* dDb = g_dD + ((size_t)(b * Mn + m0)) * Hn;
    #pragma unroll
    for (int i = 0; i < 2; i++) {
        #pragma unroll
        for (int h2 = 0; h2 < 2; h2++) {
            const int ml = warpm * 32 + i * 16 + 8 * h2 + g8;
            const float* drow = dDb + (size_t)ml * Hn + warph * 128 + 2 * t4;
            float sum = 0.f, ssq = 0.f;
            #pragma unroll
            for (int j = 0; j < 16; j++) {
                const int h = warph * 128 + j * 8 + 2 * t4;
                const float2 dd = *(const float2*)(drow + j * 8);
                const float2 av = __half22float2(
                    *(const __half2*)&acc16[i][j][h2]);
                const float v0 = av.x + sTA[h]     + dd.x;
                const float v1 = av.y + sTA[h + 1] + dd.y;
                sum += v0 + v1;
                ssq += v0 * v0 + v1 * v1;
                const __half2 hv = __floats2half2_rn(v0, v1);
                sV[(((i * 2 + h2) * 16 + j) << 8) + tid] = *(const uint32_t*)&hv;
            }
            sum += __shfl_xor_sync(0xffffffffu, sum, 1);
            sum += __shfl_xor_sync(0xffffffffu, sum, 2);
            ssq += __shfl_xor_sync(0xffffffffu, ssq, 1);
            ssq += __shfl_xor_sync(0xffffffffu, ssq, 2);
            if (t4 == 0) { sSum[warph * 64 + ml] = sum; sSsq[warph * 64 + ml] = ssq; }
        }
    }
    __syncthreads();
    if (tid < 64) {
        float s = sSum[tid] + sSum[64 + tid] + sSum[128 + tid] + sSum[192 + tid];
        float q = sSsq[tid] + sSsq[64 + tid] + sSsq[128 + tid] + sSsq[192 + tid];
        const float mu  = s * (1.f / 512.f);
        const float var = q * (1.f / 512.f) - mu * mu;
        sMu[tid] = mu;
        sRs[tid] = rsqrtf(var + 1e-5f);
    }
    __syncthreads();

    // ---- epilogue pass 2: LN, SiLU, W2 dot (v from stash) ----
    #pragma unroll
    for (int i = 0; i < 2; i++) {
        #pragma unroll
        for (int h2 = 0; h2 < 2; h2++) {
            const int ml = warpm * 32 + i * 16 + 8 * h2 + g8;
            const float mu = sMu[ml], rs = sRs[ml];
            float dot = 0.f;
            #pragma unroll
            for (int j = 0; j < 16; j++) {
                const int h = warph * 128 + j * 8 + 2 * t4;
                const uint32_t w = sV[(((i * 2 + h2) * 16 + j) << 8) + tid];
                const float2 v = __half22float2(*(const __half2*)&w);
                const float y0 = (v.x - mu) * rs * sG[h]     + sBt[h];
                const float y1 = (v.y - mu) * rs * sG[h + 1] + sBt[h + 1];
                dot += (y0 * sigmoid_fast(y0)) * sW2[h];
                dot += (y1 * sigmoid_fast(y1)) * sW2[h + 1];
            }
            dot += __shfl_xor_sync(0xffffffffu, dot, 1);
            dot += __shfl_xor_sync(0xffffffffu, dot, 2);
            if (t4 == 0) sDot[warph * 64 + ml] = dot;
        }
    }
    __syncthreads();
    if (tid < 64) {
        const float d = sDot[tid] + sDot[64 + tid] + sDot[128 + tid]
                      + sDot[192 + tid] + b2[0];
        out[(size_t)pr * Mn + m0 + tid] = d;
    }
}

// ---------------------------------------------------------------------------
extern "C" void kernel_launch(void* const* d_in, const int* in_sizes, int n_in,
                              void* d_out, int out_size) {
    const float* track = (const float*)d_in[0];
    const float* det   = (const float*)d_in[1];
    const float* W1    = (const float*)d_in[2];
    const float* b1    = (const float*)d_in[3];
    const float* gamma = (const float*)d_in[4];
    const float* beta  = (const float*)d_in[5];
    const float* W2    = (const float*)d_in[6];
    const float* b2    = (const float*)d_in[7];
    float* out = (float*)d_out;

    cudaFuncSetAttribute(main_kernel,
                         cudaFuncAttributeMaxDynamicSharedMemorySize, SMEM_BYTES);

    wh_kernel<<<256, 256>>>(W1);
    prep_kernel<<<128, 256>>>(track, det, W1, b1);
    main_kernel<<<2 * Bn * Nn, 256, SMEM_BYTES>>>(gamma, beta, W2, b2, out);
}